// round 12
// baseline (speedup 1.0000x reference)
#include <cuda_runtime.h>

#define DFEAT 64
#define DF4 (DFEAT / 4)     // 16 float4 per row
#define MAX_NODES 50000
#define MAX_EDGES 800000
#define SCAN_B 1024
#define MAX_BLK ((MAX_NODES + SCAN_B - 1) / SCAN_B)

// ---- scratch (device globals; no allocation allowed) ----
__device__ int    g_deg[MAX_NODES];
__device__ int    g_cnt[MAX_NODES];
__device__ float  g_dinv[MAX_NODES];
__device__ int    g_rowptr[MAX_NODES + 1];
__device__ int    g_cursor[MAX_NODES];
__device__ int    g_bsum[MAX_BLK];
__device__ int2   g_edge[MAX_EDGES];            // {col, float_as_int(w)}
__device__ float4 g_x1[MAX_NODES * DF4];
__device__ float4 g_x2[MAX_NODES * DF4];

__global__ void k_zero(int n) {
    int i = blockIdx.x * blockDim.x + threadIdx.x;
    if (i < n) { g_deg[i] = 0; g_cnt[i] = 0; }
}

__global__ void k_count(const int* __restrict__ src, const int* __restrict__ dst, int E) {
    int e = blockIdx.x * blockDim.x + threadIdx.x;
    if (e < E) {
        atomicAdd(&g_deg[src[e]], 1);
        atomicAdd(&g_cnt[dst[e]], 1);
    }
}

// Fused: blocks [0, nb) per-block scan of g_cnt; blocks [nb, 2nb) compute dinv.
__global__ void k_prep(int n, int nb) {
    if ((int)blockIdx.x < nb) {
        __shared__ int s[SCAN_B];
        int t = threadIdx.x;
        int i = blockIdx.x * SCAN_B + t;
        int v = (i < n) ? g_cnt[i] : 0;
        s[t] = v;
        __syncthreads();
        for (int off = 1; off < SCAN_B; off <<= 1) {
            int u = (t >= off) ? s[t - off] : 0;
            __syncthreads();
            s[t] += u;
            __syncthreads();
        }
        if (i < n) g_rowptr[i] = s[t] - v;
        if (t == SCAN_B - 1) g_bsum[blockIdx.x] = s[t];
    } else {
        int i = (blockIdx.x - nb) * SCAN_B + threadIdx.x;
        if (i < n) {
            int d = g_deg[i];
            g_dinv[i] = (d > 0) ? rsqrtf((float)d) : 0.0f;
        }
    }
}

// Scan phases 2+3: parallel tile-sum scan + offset add.
__global__ void k_scan3(int n, int nb) {
    __shared__ int s[64];    // nb <= 49
    int t = threadIdx.x;
    if (t < 64) s[t] = (t < nb) ? g_bsum[t] : 0;
    __syncthreads();
    if (t < 64) {
        for (int off = 1; off < 64; off <<= 1) {
            int u = (t >= off) ? s[t - off] : 0;
            __syncthreads();
            s[t] += u;
            __syncthreads();
        }
    } else {
        for (int off = 1; off < 64; off <<= 1) { __syncthreads(); __syncthreads(); }
    }
    int b = (int)blockIdx.x;
    int pref = (b > 0) ? s[b - 1] : 0;
    if (b == nb - 1 && t == 0) g_rowptr[n] = s[nb - 1];
    int i = b * SCAN_B + t;
    if (i < n) {
        int r = g_rowptr[i] + pref;
        g_rowptr[i] = r;
        g_cursor[i] = r;
    }
}

__global__ void k_fill(const int* __restrict__ src, const int* __restrict__ dst, int E) {
    int e = blockIdx.x * blockDim.x + threadIdx.x;
    if (e < E) {
        int d = dst[e];
        int s = src[e];
        int pos = atomicAdd(&g_cursor[d], 1);
        g_edge[pos] = make_int2(s, __float_as_int(g_dinv[s] * g_dinv[d]));
    }
}

// One row per HALF-WARP, depth-2 software-pipelined gather loop:
// next batch's edge loads + gathers are issued BEFORE the current batch's
// FMAs consume (and scoreboard-wait on) their values, overlapping the L2
// round trips of consecutive batches.
__global__ void k_spmm(const float* __restrict__ feat, float* __restrict__ h,
                       float theta, int init, int xin_sel, int xout_sel, int n) {
    int row = (blockIdx.x * blockDim.x + threadIdx.x) >> 4;
    int qi  = threadIdx.x & 15;
    if (row >= n) return;

    const float4* __restrict__ x =
        (xin_sel == 0) ? reinterpret_cast<const float4*>(feat)
                       : ((xin_sel == 1) ? (const float4*)g_x1 : (const float4*)g_x2);
    float4* xout = (xout_sel == 0) ? (float4*)0 : ((xout_sel == 1) ? g_x1 : g_x2);

    int beg = g_rowptr[row];
    int end = g_rowptr[row + 1];

    float4 acc = make_float4(0.f, 0.f, 0.f, 0.f);
    int p = beg;

    if (p + 4 <= end) {
        // Prologue: load batch 0 edges, issue its gathers.
        int2 ea0 = g_edge[p],     ea1 = g_edge[p + 1];
        int2 ea2 = g_edge[p + 2], ea3 = g_edge[p + 3];
        float4 va0 = x[ea0.x * DF4 + qi];
        float4 va1 = x[ea1.x * DF4 + qi];
        float4 va2 = x[ea2.x * DF4 + qi];
        float4 va3 = x[ea3.x * DF4 + qi];
        p += 4;

        while (p + 4 <= end) {
            // Issue next batch's loads FIRST...
            int2 eb0 = g_edge[p],     eb1 = g_edge[p + 1];
            int2 eb2 = g_edge[p + 2], eb3 = g_edge[p + 3];
            float4 vb0 = x[eb0.x * DF4 + qi];
            float4 vb1 = x[eb1.x * DF4 + qi];
            float4 vb2 = x[eb2.x * DF4 + qi];
            float4 vb3 = x[eb3.x * DF4 + qi];
            // ...then consume the current batch (waits overlap the in-flight loads).
            float w0 = __int_as_float(ea0.y), w1 = __int_as_float(ea1.y);
            float w2 = __int_as_float(ea2.y), w3 = __int_as_float(ea3.y);
            acc.x = fmaf(w0, va0.x, acc.x); acc.y = fmaf(w0, va0.y, acc.y);
            acc.z = fmaf(w0, va0.z, acc.z); acc.w = fmaf(w0, va0.w, acc.w);
            acc.x = fmaf(w1, va1.x, acc.x); acc.y = fmaf(w1, va1.y, acc.y);
            acc.z = fmaf(w1, va1.z, acc.z); acc.w = fmaf(w1, va1.w, acc.w);
            acc.x = fmaf(w2, va2.x, acc.x); acc.y = fmaf(w2, va2.y, acc.y);
            acc.z = fmaf(w2, va2.z, acc.z); acc.w = fmaf(w2, va2.w, acc.w);
            acc.x = fmaf(w3, va3.x, acc.x); acc.y = fmaf(w3, va3.y, acc.y);
            acc.z = fmaf(w3, va3.z, acc.z); acc.w = fmaf(w3, va3.w, acc.w);
            ea0 = eb0; ea1 = eb1; ea2 = eb2; ea3 = eb3;
            va0 = vb0; va1 = vb1; va2 = vb2; va3 = vb3;
            p += 4;
        }
        // Drain the last full batch.
        float w0 = __int_as_float(ea0.y), w1 = __int_as_float(ea1.y);
        float w2 = __int_as_float(ea2.y), w3 = __int_as_float(ea3.y);
        acc.x = fmaf(w0, va0.x, acc.x); acc.y = fmaf(w0, va0.y, acc.y);
        acc.z = fmaf(w0, va0.z, acc.z); acc.w = fmaf(w0, va0.w, acc.w);
        acc.x = fmaf(w1, va1.x, acc.x); acc.y = fmaf(w1, va1.y, acc.y);
        acc.z = fmaf(w1, va1.z, acc.z); acc.w = fmaf(w1, va1.w, acc.w);
        acc.x = fmaf(w2, va2.x, acc.x); acc.y = fmaf(w2, va2.y, acc.y);
        acc.z = fmaf(w2, va2.z, acc.z); acc.w = fmaf(w2, va2.w, acc.w);
        acc.x = fmaf(w3, va3.x, acc.x); acc.y = fmaf(w3, va3.y, acc.y);
        acc.z = fmaf(w3, va3.z, acc.z); acc.w = fmaf(w3, va3.w, acc.w);
    }
    // Scalar tail (0-3 edges).
    for (; p < end; p++) {
        int2 e = g_edge[p];
        float w = __int_as_float(e.y);
        float4 v = x[e.x * DF4 + qi];
        acc.x = fmaf(w, v.x, acc.x); acc.y = fmaf(w, v.y, acc.y);
        acc.z = fmaf(w, v.z, acc.z); acc.w = fmaf(w, v.w, acc.w);
    }

    int o = row * DF4 + qi;
    if (xout) xout[o] = acc;
    float4* h4 = reinterpret_cast<float4*>(h);
    if (init) {
        h4[o] = make_float4(theta * acc.x, theta * acc.y,
                            theta * acc.z, theta * acc.w);
    } else {
        float4 c = h4[o];
        c.x = fmaf(theta, acc.x, c.x);
        c.y = fmaf(theta, acc.y, c.y);
        c.z = fmaf(theta, acc.z, c.z);
        c.w = fmaf(theta, acc.w, c.w);
        h4[o] = c;
    }
}

extern "C" void kernel_launch(void* const* d_in, const int* in_sizes, int n_in,
                              void* d_out, int out_size) {
    const float* feat = (const float*)d_in[0];
    const int*   src  = (const int*)d_in[1];
    const int*   dst  = (const int*)d_in[2];
    float*       h    = (float*)d_out;

    int n = in_sizes[0] / DFEAT;   // 50000
    int E = in_sizes[1];           // 800000

    int tb = 256;
    int gn = (n + tb - 1) / tb;
    int ge = (E + tb - 1) / tb;
    int nb = (n + SCAN_B - 1) / SCAN_B;

    k_zero<<<gn, tb>>>(n);
    k_count<<<ge, tb>>>(src, dst, E);
    k_prep<<<2 * nb, SCAN_B>>>(n, nb);
    k_scan3<<<nb, SCAN_B>>>(n, nb);
    k_fill<<<ge, tb>>>(src, dst, E);

    int gs = (n + 15) / 16;   // one row per half-warp, 16 half-warps/block
    // h  = 0.80 * (A @ f)      ; x1 -> g_x1
    k_spmm<<<gs, tb>>>(feat, h, 0.80f, 1, 0, 1, n);
    // h += 0.15 * (A @ x1)     ; x2 -> g_x2
    k_spmm<<<gs, tb>>>(feat, h, 0.15f, 0, 1, 2, n);
    // h += 0.05 * (A @ x2)
    k_spmm<<<gs, tb>>>(feat, h, 0.05f, 0, 2, 0, n);
}

// round 13
// speedup vs baseline: 1.2181x; 1.2181x over previous
#include <cuda_runtime.h>
#include <cuda_fp16.h>

#define DFEAT 64
#define DQ 16               // 16 uint2 (4 halves each) per fp16 row
#define MAX_NODES 50000
#define MAX_EDGES 800000
#define SCAN_B 1024
#define MAX_BLK ((MAX_NODES + SCAN_B - 1) / SCAN_B)

// ---- scratch (device globals; no allocation allowed) ----
__device__ int   g_deg[MAX_NODES];
__device__ int   g_cnt[MAX_NODES];
__device__ float g_dinv[MAX_NODES];
__device__ int   g_rowptr[MAX_NODES + 1];
__device__ int   g_cursor[MAX_NODES];
__device__ int   g_bsum[MAX_BLK];
__device__ int2  g_edge[MAX_EDGES];             // {col, float_as_int(w)}
__device__ uint2 g_hx0[MAX_NODES * DQ];         // feat in fp16
__device__ uint2 g_hx1[MAX_NODES * DQ];         // hop-1 result in fp16
__device__ uint2 g_hx2[MAX_NODES * DQ];         // hop-2 result in fp16

__global__ void k_zero(int n) {
    int i = blockIdx.x * blockDim.x + threadIdx.x;
    if (i < n) { g_deg[i] = 0; g_cnt[i] = 0; }
}

__global__ void k_count(const int* __restrict__ src, const int* __restrict__ dst, int E) {
    int e = blockIdx.x * blockDim.x + threadIdx.x;
    if (e < E) {
        atomicAdd(&g_deg[src[e]], 1);
        atomicAdd(&g_cnt[dst[e]], 1);
    }
}

// Fused (all three groups depend only on k_count / feat):
//   blocks [0, nb)        : per-tile scan of g_cnt
//   blocks [nb, 2nb)      : d^{-1/2}
//   blocks [2nb, 2nb+ncv) : feat fp32 -> fp16 conversion
__global__ void k_prep(const float* __restrict__ feat, int n, int nb, int ncv) {
    int b = (int)blockIdx.x;
    if (b < nb) {
        __shared__ int s[SCAN_B];
        int t = threadIdx.x;
        int i = b * SCAN_B + t;
        int v = (i < n) ? g_cnt[i] : 0;
        s[t] = v;
        __syncthreads();
        for (int off = 1; off < SCAN_B; off <<= 1) {
            int u = (t >= off) ? s[t - off] : 0;
            __syncthreads();
            s[t] += u;
            __syncthreads();
        }
        if (i < n) g_rowptr[i] = s[t] - v;
        if (t == SCAN_B - 1) g_bsum[b] = s[t];
    } else if (b < 2 * nb) {
        int i = (b - nb) * SCAN_B + threadIdx.x;
        if (i < n) {
            int d = g_deg[i];
            g_dinv[i] = (d > 0) ? rsqrtf((float)d) : 0.0f;
        }
    } else {
        // convert: each thread turns one float4 of feat into one uint2 of halves
        int i = (b - 2 * nb) * SCAN_B + threadIdx.x;
        int tot = n * DQ;
        if (i < tot) {
            float4 f = reinterpret_cast<const float4*>(feat)[i];
            __half2 h0 = __floats2half2_rn(f.x, f.y);
            __half2 h1 = __floats2half2_rn(f.z, f.w);
            uint2 u;
            u.x = *reinterpret_cast<unsigned*>(&h0);
            u.y = *reinterpret_cast<unsigned*>(&h1);
            g_hx0[i] = u;
        }
    }
}

// Scan phases 2+3: parallel tile-sum scan + offset add.
__global__ void k_scan3(int n, int nb) {
    __shared__ int s[64];    // nb <= 49
    int t = threadIdx.x;
    if (t < 64) s[t] = (t < nb) ? g_bsum[t] : 0;
    __syncthreads();
    if (t < 64) {
        for (int off = 1; off < 64; off <<= 1) {
            int u = (t >= off) ? s[t - off] : 0;
            __syncthreads();
            s[t] += u;
            __syncthreads();
        }
    } else {
        for (int off = 1; off < 64; off <<= 1) { __syncthreads(); __syncthreads(); }
    }
    int b = (int)blockIdx.x;
    int pref = (b > 0) ? s[b - 1] : 0;
    if (b == nb - 1 && t == 0) g_rowptr[n] = s[nb - 1];
    int i = b * SCAN_B + t;
    if (i < n) {
        int r = g_rowptr[i] + pref;
        g_rowptr[i] = r;
        g_cursor[i] = r;
    }
}

__global__ void k_fill(const int* __restrict__ src, const int* __restrict__ dst, int E) {
    int e = blockIdx.x * blockDim.x + threadIdx.x;
    if (e < E) {
        int d = dst[e];
        int s = src[e];
        int pos = atomicAdd(&g_cursor[d], 1);
        g_edge[pos] = make_int2(s, __float_as_int(g_dinv[s] * g_dinv[d]));
    }
}

__device__ __forceinline__ void hacc(float4& acc, float w, uint2 raw) {
    __half2 h0 = *reinterpret_cast<__half2*>(&raw.x);
    __half2 h1 = *reinterpret_cast<__half2*>(&raw.y);
    float2 f0 = __half22float2(h0);
    float2 f1 = __half22float2(h1);
    acc.x = fmaf(w, f0.x, acc.x);
    acc.y = fmaf(w, f0.y, acc.y);
    acc.z = fmaf(w, f1.x, acc.z);
    acc.w = fmaf(w, f1.y, acc.w);
}

// One row per HALF-WARP (R11 structure). fp16 gathers: lane qi loads one
// uint2 (4 halves) per edge -> 128B per row per edge (half of fp32).
// Accumulation is fp32. xin/xout select the fp16 ping-pong buffers.
__global__ void k_spmm(float* __restrict__ h, float theta, int init,
                       int xin_sel, int xout_sel, int n) {
    int row = (blockIdx.x * blockDim.x + threadIdx.x) >> 4;
    int qi  = threadIdx.x & 15;
    if (row >= n) return;

    const uint2* __restrict__ x =
        (xin_sel == 0) ? g_hx0 : ((xin_sel == 1) ? g_hx1 : g_hx2);
    uint2* xout = (xout_sel == 0) ? (uint2*)0 : ((xout_sel == 1) ? g_hx1 : g_hx2);

    int beg = g_rowptr[row];
    int end = g_rowptr[row + 1];

    float4 acc = make_float4(0.f, 0.f, 0.f, 0.f);

    int p = beg;
    for (; p + 4 <= end; p += 4) {
        int2 e0 = g_edge[p],     e1 = g_edge[p + 1];
        int2 e2 = g_edge[p + 2], e3 = g_edge[p + 3];
        uint2 v0 = x[e0.x * DQ + qi];
        uint2 v1 = x[e1.x * DQ + qi];
        uint2 v2 = x[e2.x * DQ + qi];
        uint2 v3 = x[e3.x * DQ + qi];
        hacc(acc, __int_as_float(e0.y), v0);
        hacc(acc, __int_as_float(e1.y), v1);
        hacc(acc, __int_as_float(e2.y), v2);
        hacc(acc, __int_as_float(e3.y), v3);
    }
    for (; p < end; p++) {
        int2 e = g_edge[p];
        uint2 v = x[e.x * DQ + qi];
        hacc(acc, __int_as_float(e.y), v);
    }

    int o = row * DQ + qi;
    if (xout) {
        __half2 h0 = __floats2half2_rn(acc.x, acc.y);
        __half2 h1 = __floats2half2_rn(acc.z, acc.w);
        uint2 u;
        u.x = *reinterpret_cast<unsigned*>(&h0);
        u.y = *reinterpret_cast<unsigned*>(&h1);
        xout[o] = u;
    }
    float4* h4 = reinterpret_cast<float4*>(h);
    if (init) {
        h4[o] = make_float4(theta * acc.x, theta * acc.y,
                            theta * acc.z, theta * acc.w);
    } else {
        float4 c = h4[o];
        c.x = fmaf(theta, acc.x, c.x);
        c.y = fmaf(theta, acc.y, c.y);
        c.z = fmaf(theta, acc.z, c.z);
        c.w = fmaf(theta, acc.w, c.w);
        h4[o] = c;
    }
}

extern "C" void kernel_launch(void* const* d_in, const int* in_sizes, int n_in,
                              void* d_out, int out_size) {
    const float* feat = (const float*)d_in[0];
    const int*   src  = (const int*)d_in[1];
    const int*   dst  = (const int*)d_in[2];
    float*       h    = (float*)d_out;

    int n = in_sizes[0] / DFEAT;   // 50000
    int E = in_sizes[1];           // 800000

    int tb = 256;
    int gn = (n + tb - 1) / tb;
    int ge = (E + tb - 1) / tb;
    int nb = (n + SCAN_B - 1) / SCAN_B;
    int ncv = (n * DQ + SCAN_B - 1) / SCAN_B;   // conversion blocks

    k_zero<<<gn, tb>>>(n);
    k_count<<<ge, tb>>>(src, dst, E);
    k_prep<<<2 * nb + ncv, SCAN_B>>>(feat, n, nb, ncv);
    k_scan3<<<nb, SCAN_B>>>(n, nb);
    k_fill<<<ge, tb>>>(src, dst, E);

    int gs = (n + 15) / 16;   // one row per half-warp
    // h  = 0.80 * (A @ f)      ; x1 -> g_hx1
    k_spmm<<<gs, tb>>>(h, 0.80f, 1, 0, 1, n);
    // h += 0.15 * (A @ x1)     ; x2 -> g_hx2
    k_spmm<<<gs, tb>>>(h, 0.15f, 0, 1, 2, n);
    // h += 0.05 * (A @ x2)
    k_spmm<<<gs, tb>>>(h, 0.05f, 0, 2, 0, n);
}